// round 13
// baseline (speedup 1.0000x reference)
#include <cuda_runtime.h>

typedef unsigned long long u64;
typedef unsigned int u32;
#define FULLMASK 0xffffffffu

constexpr int NWARPS   = 11;
constexpr int NTHREADS = NWARPS * 32;     // 352
constexpr int NGROUPS  = 24576 / 16;      // 1536 groups of 16 rows

// ---- shared memory layout (float offsets) ----
constexpr int OFF_W1F = 0;          // uint4[4][32][32] W1 frags (hi01,hi23,lo01,lo23) = 16384 floats
constexpr int OFF_W2F = 16384;      // uint4[16][8][32] W2 frags = 16384 floats
constexpr int OFF_B1  = 32768;      // 256
constexpr int OFF_B2  = 33024;      // 64
constexpr int OFF_WE  = 33088;      // 128
constexpr int OFF_BE  = 33216;      // 64
constexpr int OFF_M   = 33280;      // 40
constexpr int OFF_A0  = 33320;      // 256
constexpr int OFF_A1  = 33576;      // 256
constexpr int OFF_K   = 33832;      // 64
constexpr int OFF_G2  = 33896;      // 64
constexpr int OFF_LB2 = 33960;      // 64
constexpr int OFF_DUP = 34024;      // 4 x 64: g1lo, g1hi, lb1lo, lb1hi
constexpr int OFF_SCR = 34280;      // per-warp scratch
constexpr int SCR_FLOATS = 1280;    // sx [0,1152) f32[16][72]; pkb aliases [0,1088) stride-34; uvb [1152,1280)
constexpr int SMEM_FLOATS = OFF_SCR + NWARPS * SCR_FLOATS;  // 48360 -> 193440 B

// ---- f32x2 / misc helpers ----
__device__ __forceinline__ u64 pk2(float lo, float hi) {
    u64 r; asm("mov.b64 %0,{%1,%2};" : "=l"(r) : "f"(lo), "f"(hi)); return r;
}
__device__ __forceinline__ u64 dup2(float v) { return pk2(v, v); }
__device__ __forceinline__ void un2(u64 v, float& a, float& b) {
    asm("mov.b64 {%0,%1},%2;" : "=f"(a), "=f"(b) : "l"(v));
}
__device__ __forceinline__ u64 f2fma(u64 a, u64 b, u64 c) {
    u64 d; asm("fma.rn.f32x2 %0,%1,%2,%3;" : "=l"(d) : "l"(a), "l"(b), "l"(c)); return d;
}
__device__ __forceinline__ u64 f2add(u64 a, u64 b) {
    u64 d; asm("add.rn.f32x2 %0,%1,%2;" : "=l"(d) : "l"(a), "l"(b)); return d;
}
__device__ __forceinline__ u64 f2mul(u64 a, u64 b) {
    u64 d; asm("mul.rn.f32x2 %0,%1,%2;" : "=l"(d) : "l"(a), "l"(b)); return d;
}
__device__ __forceinline__ float ex2f(float x) {
    float y; asm("ex2.approx.f32 %0,%1;" : "=f"(y) : "f"(x)); return y;
}
__device__ __forceinline__ float bfly_add(float v) {
    #pragma unroll
    for (int o = 16; o >= 1; o >>= 1) v += __shfl_xor_sync(FULLMASK, v, o);
    return v;
}
// pack two f32 into bf16x2 (lo -> low half, hi -> high half)
__device__ __forceinline__ u32 pkbf(float hi, float lo) {
    u32 d; asm("cvt.rn.bf16x2.f32 %0,%1,%2;" : "=r"(d) : "f"(hi), "f"(lo)); return d;
}
__device__ __forceinline__ float bflo(u32 h) { return __uint_as_float(h << 16); }
__device__ __forceinline__ float bfhi(u32 h) { return __uint_as_float(h & 0xffff0000u); }

// m16n8k16 row.col bf16 mma, D = A*B + D
__device__ __forceinline__ void mma16816(float4& c, const u32* a, u32 b0, u32 b1) {
    asm volatile(
        "mma.sync.aligned.m16n8k16.row.col.f32.bf16.bf16.f32 "
        "{%0,%1,%2,%3},{%4,%5,%6,%7},{%8,%9},{%0,%1,%2,%3};"
        : "+f"(c.x), "+f"(c.y), "+f"(c.z), "+f"(c.w)
        : "r"(a[0]), "r"(a[1]), "r"(a[2]), "r"(a[3]), "r"(b0), "r"(b1));
}

// layernorm on row-pairs packed in f32x2
__device__ __forceinline__ void ln_pair(u64 vlo, u64 vhi, u64 glo, u64 ghi, u64 blo, u64 bhi,
                                        u64& xlo, u64& xhi) {
    float sa, sb; un2(f2add(vlo, vhi), sa, sb);
    sa = bfly_add(sa); sb = bfly_add(sb);
    u64 mun = f2mul(pk2(sa, sb), dup2(-1.0f / 64.0f));
    u64 dlo = f2add(vlo, mun), dhi = f2add(vhi, mun);
    float qa, qb; un2(f2fma(dlo, dlo, f2mul(dhi, dhi)), qa, qb);
    qa = bfly_add(qa); qb = bfly_add(qb);
    float ra = rsqrtf(fmaf(qa, 1.0f / 64.0f, 1e-5f));
    float rb = rsqrtf(fmaf(qb, 1.0f / 64.0f, 1e-5f));
    u64 rs = pk2(ra, rb);
    xlo = f2fma(f2mul(dlo, rs), glo, blo);
    xhi = f2fma(f2mul(dhi, rs), ghi, bhi);
}

__global__ void __launch_bounds__(NTHREADS, 1)
main_kernel(const float* __restrict__ prec, const int* __restrict__ topmask,
            const float* __restrict__ We, const float* __restrict__ be,
            const float* __restrict__ Wq, const float* __restrict__ Wk,
            const float* __restrict__ Wv, const float* __restrict__ Wo,
            const float* __restrict__ bo,
            const float* __restrict__ g1, const float* __restrict__ lb1,
            const float* __restrict__ W1, const float* __restrict__ b1,
            const float* __restrict__ W2, const float* __restrict__ b2,
            const float* __restrict__ g2, const float* __restrict__ lb2,
            float* __restrict__ out)
{
    extern __shared__ float sm[];
    const int tid = threadIdx.x;

    // ---- fragment-ordered bf16 hi/lo conversion of W1, W2 (one-time) ----
    for (int idx = tid; idx < 8192; idx += NTHREADS) {
        float w00, w01, w10, w11;
        uint4* dst;
        if (idx < 4096) {
            int kt = idx >> 10, nt = (idx >> 5) & 31, t = idx & 31;
            int k = 16 * kt + 2 * (t & 3), n = 8 * nt + (t >> 2);
            w00 = W1[k * 256 + n];       w01 = W1[(k + 1) * 256 + n];
            w10 = W1[(k + 8) * 256 + n]; w11 = W1[(k + 9) * 256 + n];
            dst = (uint4*)(sm + OFF_W1F) + idx;
        } else {
            int j = idx - 4096;
            int hcb = j >> 8, nt = (j >> 5) & 7, t = j & 31;
            int k = 16 * hcb + 2 * (t & 3), n = 8 * nt + (t >> 2);
            w00 = W2[k * 64 + n];       w01 = W2[(k + 1) * 64 + n];
            w10 = W2[(k + 8) * 64 + n]; w11 = W2[(k + 9) * 64 + n];
            dst = (uint4*)(sm + OFF_W2F) + j;
        }
        u32 hi0 = pkbf(w01, w00), hi1 = pkbf(w11, w10);
        u32 lo0 = pkbf(w01 - bfhi(hi0), w00 - bflo(hi0));
        u32 lo1 = pkbf(w11 - bfhi(hi1), w10 - bflo(hi1));
        *dst = make_uint4(hi0, hi1, lo0, lo1);
    }

    // ---- stage small arrays ----
    if (tid < 256) sm[OFF_B1 + tid] = b1[tid];
    if (tid < 128) sm[OFF_WE + tid] = We[tid];
    if (tid < 64) {
        sm[OFF_BE + tid]  = be[tid];
        sm[OFF_B2 + tid]  = b2[tid];
        sm[OFF_G2 + tid]  = g2[tid];
        sm[OFF_LB2 + tid] = lb2[tid];
    }
    if (tid >= 256 && tid < 288) {
        int t = tid - 256;
        float v;
        v = g1[t];       sm[OFF_DUP + 0 * 64 + 2 * t] = v; sm[OFF_DUP + 0 * 64 + 2 * t + 1] = v;
        v = g1[32 + t];  sm[OFF_DUP + 1 * 64 + 2 * t] = v; sm[OFF_DUP + 1 * 64 + 2 * t + 1] = v;
        v = lb1[t];      sm[OFF_DUP + 2 * 64 + 2 * t] = v; sm[OFF_DUP + 2 * 64 + 2 * t + 1] = v;
        v = lb1[32 + t]; sm[OFF_DUP + 3 * 64 + 2 * t] = v; sm[OFF_DUP + 3 * 64 + 2 * t + 1] = v;
    }

    // ---- setup stage 1: combined QKV embed weights (temps in warp0 scratch) ----
    float* tWQ = sm + OFF_SCR;
    float* tWK = tWQ + 128;
    float* tWV = tWK + 128;
    float* tbQ = tWV + 128;
    float* tbK = tbQ + 64;
    float* tbV = tbK + 64;
    if (tid < 64) {
        int j = tid, h = j >> 4, d = j & 15;
        float q0 = 0.f, q1 = 0.f, k0 = 0.f, k1 = 0.f, v0 = 0.f, v1 = 0.f;
        float bq = 0.f, bk = 0.f, bv = 0.f;
        for (int e = 0; e < 16; e++) {
            float we0 = We[h * 16 + e];
            float we1 = We[64 + h * 16 + e];
            float bb  = be[h * 16 + e];
            float wq = Wq[e * 16 + d], wk = Wk[e * 16 + d], wv = Wv[e * 16 + d];
            q0 = fmaf(we0, wq, q0); q1 = fmaf(we1, wq, q1); bq = fmaf(bb, wq, bq);
            k0 = fmaf(we0, wk, k0); k1 = fmaf(we1, wk, k1); bk = fmaf(bb, wk, bk);
            v0 = fmaf(we0, wv, v0); v1 = fmaf(we1, wv, v1); bv = fmaf(bb, wv, bv);
        }
        tWQ[j] = q0; tWQ[64 + j] = q1; tbQ[j] = bq;
        tWK[j] = k0; tWK[64 + j] = k1; tbK[j] = bk;
        tWV[j] = v0; tWV[64 + j] = v1; tbV[j] = bv;
    }
    __syncthreads();

    // ---- setup stage 2: bilinear energy forms + folded Wo ----
    if (tid < 4) {
        const float SC = 0.125f * 1.4426950408889634f;   // 1/sqrt(E) + log2e fold
        int hh = tid;
        float m00=0,m01=0,m02=0,m10=0,m11=0,m12=0,m20=0,m21=0,m22=0;
        for (int dd = 0; dd < 16; dd++) {
            float Q0 = tWQ[hh*16+dd], Q1 = tWQ[64+hh*16+dd], BQ = tbQ[hh*16+dd];
            float K0 = tWK[hh*16+dd], K1 = tWK[64+hh*16+dd], BK = tbK[hh*16+dd];
            m00 += Q0*K0; m01 += Q0*K1; m02 += Q0*BK;
            m10 += Q1*K0; m11 += Q1*K1; m12 += Q1*BK;
            m20 += BQ*K0; m21 += BQ*K1; m22 += BQ*BK;
        }
        sm[OFF_M+hh*9+0]=m00*SC; sm[OFF_M+hh*9+1]=m01*SC; sm[OFF_M+hh*9+2]=m02*SC;
        sm[OFF_M+hh*9+3]=m10*SC; sm[OFF_M+hh*9+4]=m11*SC; sm[OFF_M+hh*9+5]=m12*SC;
        sm[OFF_M+hh*9+6]=m20*SC; sm[OFF_M+hh*9+7]=m21*SC; sm[OFF_M+hh*9+8]=m22*SC;
    }
    if (tid >= 64 && tid < 128) {
        int j = tid - 64;
        float kk = 0.f;
        for (int hh = 0; hh < 4; hh++) {
            float s0 = 0.f, s1 = 0.f;
            for (int dd = 0; dd < 16; dd++) {
                int row = hh * 16 + dd;
                float w = Wo[row * 64 + j];
                s0 = fmaf(tWV[row], w, s0);
                s1 = fmaf(tWV[64 + row], w, s1);
                kk = fmaf(tbV[row], w, kk);
            }
            sm[OFF_A0 + hh * 64 + j] = s0;
            sm[OFF_A1 + hh * 64 + j] = s1;
        }
        sm[OFF_K + j] = kk + bo[j];
    }
    __syncthreads();

    const int warp = tid >> 5;
    const int L = tid & 31;
    float* scr   = sm + OFF_SCR + warp * SCR_FLOATS;
    float* sx    = scr;                    // f32 [16][72]
    float2* pkb  = (float2*)scr;           // [16][34] (px,py) — aliases sx, float4-aligned rows
    u64* uvb     = (u64*)(scr + 1152);     // [64] (u,v) per (row,head)
    const uint4* w1f = (const uint4*)(sm + OFF_W1F);
    const uint4* w2f = (const uint4*)(sm + OFF_W2F);

    // per-lane constants
    const float we0l = sm[OFF_WE + L],      we1l = sm[OFF_WE + 64 + L],  bel = sm[OFF_BE + L];
    const float we0h = sm[OFF_WE + 32 + L], we1h = sm[OFF_WE + 96 + L], beh = sm[OFF_BE + 32 + L];
    u64 a0p[4], a1p[4];
    #pragma unroll
    for (int h = 0; h < 4; h++) {
        a0p[h] = pk2(sm[OFF_A0 + h * 64 + L], sm[OFF_A0 + h * 64 + 32 + L]);
        a1p[h] = pk2(sm[OFF_A1 + h * 64 + L], sm[OFF_A1 + h * 64 + 32 + L]);
    }
    const u64 kv2 = pk2(sm[OFF_K + L], sm[OFF_K + 32 + L]);
    const int rr = L >> 2, hh = L & 3;
    const int fr = L >> 2, fc = 2 * (L & 3);   // fragment row / col base
    float Mh[9];
    #pragma unroll
    for (int i = 0; i < 9; i++) Mh[i] = sm[OFF_M + hh * 9 + i];
    float2 b2v[8];
    #pragma unroll
    for (int nt = 0; nt < 8; nt++) b2v[nt] = *(const float2*)&sm[OFF_B2 + 8 * nt + fc];

    const int g0 = warp * gridDim.x + blockIdx.x;
    const int gstride = gridDim.x * NWARPS;

    for (int g = g0; g < NGROUPS; g += gstride) {
        const int m0 = g * 16;
        const int bb = m0 / 192;
        const int mk = topmask[bb * 32 + L];
        const unsigned mkbits = __ballot_sync(FULLMASK, mk != 0);
        const int kqbase = m0 & 31;          // 0 or 16

        // ---- stage keys (stride 34: float4-aligned, conflict-free) ----
        #pragma unroll
        for (int r = 0; r < 16; r++)
            pkb[r * 34 + L] = ((const float2*)prec)[(m0 + r) * 32 + L];
        __syncwarp();

        // ---- transposed softmax: lane owns head hh for rows rr and rr+8 ----
        #pragma unroll
        for (int half = 0; half < 2; half++) {
            const int row = rr + 8 * half;
            const float2 pq = pkb[row * 34 + kqbase + row];
            const float Ah = fmaf(pq.y, Mh[3], fmaf(pq.x, Mh[0], Mh[6]));
            const float Bh = fmaf(pq.y, Mh[4], fmaf(pq.x, Mh[1], Mh[7]));
            const float Ch = fmaf(pq.y, Mh[5], fmaf(pq.x, Mh[2], Mh[8]));
            float s = 0.f, u = 0.f, v = 0.f;
            const float4* rowp = (const float4*)&pkb[row * 34];
            #pragma unroll 8
            for (int k2 = 0; k2 < 16; k2++) {
                float4 t = rowp[k2];             // keys 2*k2, 2*k2+1
                float e0 = fmaf(Ah, t.x, fmaf(Bh, t.y, Ch));
                float e1 = fmaf(Ah, t.z, fmaf(Bh, t.w, Ch));
                float p0 = ((mkbits >> (2 * k2)) & 1u)     ? ex2f(e0) : 0.0f;
                float p1 = ((mkbits >> (2 * k2 + 1)) & 1u) ? ex2f(e1) : 0.0f;
                s += p0 + p1;
                u = fmaf(p0, t.x, fmaf(p1, t.z, u));
                v = fmaf(p0, t.y, fmaf(p1, t.w, v));
            }
            const float inv = __fdividef(1.0f, s);
            uvb[row * 4 + hh] = pk2(u * inv, v * inv);
        }
        __syncwarp();

        // ---- folded attention output ao[r] = (ch L, ch L+32) ----
        u64 ao[16];
        #pragma unroll
        for (int r = 0; r < 16; r++) {
            u64 a = kv2;
            #pragma unroll
            for (int h = 0; h < 4; h++) {
                const float2 uv = ((const float2*)uvb)[4 * r + h];
                a = f2fma(dup2(uv.x), a0p[h], f2fma(dup2(uv.y), a1p[h], a));
            }
            ao[r] = a;
        }

        // ---- LN1 over row pairs (q, q+8); qres read from pkb ----
        u64 x_lo[8], x_hi[8];
        {
            const u64 g1l = *(const u64*)&sm[OFF_DUP + 0 * 64 + 2 * L];
            const u64 g1h = *(const u64*)&sm[OFF_DUP + 1 * 64 + 2 * L];
            const u64 l1l = *(const u64*)&sm[OFF_DUP + 2 * 64 + 2 * L];
            const u64 l1h = *(const u64*)&sm[OFF_DUP + 3 * 64 + 2 * L];
            #pragma unroll
            for (int q = 0; q < 8; q++) {
                const float2 pqa = pkb[q * 34 + kqbase + q];
                const float2 pqb = pkb[(q + 8) * 34 + kqbase + q + 8];
                const float qla = fmaf(pqa.x, we0l, fmaf(pqa.y, we1l, bel));
                const float qha = fmaf(pqa.x, we0h, fmaf(pqa.y, we1h, beh));
                const float qlb = fmaf(pqb.x, we0l, fmaf(pqb.y, we1l, bel));
                const float qhb = fmaf(pqb.x, we0h, fmaf(pqb.y, we1h, beh));
                float al, ahv, blv, bhv;
                un2(ao[q], al, ahv); un2(ao[q + 8], blv, bhv);
                u64 vlo = pk2(al + qla, blv + qlb);
                u64 vhi = pk2(ahv + qha, bhv + qhb);
                ln_pair(vlo, vhi, g1l, g1h, l1l, l1h, x_lo[q], x_hi[q]);
            }
        }
        __syncwarp();   // all pkb reads done before sx overwrites
        #pragma unroll
        for (int q = 0; q < 8; q++) {
            float la, lbv, ha, hbv;
            un2(x_lo[q], la, lbv); un2(x_hi[q], ha, hbv);
            sx[q * 72 + L] = la;
            sx[(q + 8) * 72 + L] = lbv;
            sx[q * 72 + 32 + L] = ha;
            sx[(q + 8) * 72 + 32 + L] = hbv;
        }
        __syncwarp();

        // ---- build x A-fragments (bf16 hi/lo) ----
        u32 xh[4][4], xl[4][4];
        #pragma unroll
        for (int kt = 0; kt < 4; kt++) {
            const float2 v0 = *(const float2*)&sx[fr * 72 + 16 * kt + fc];
            const float2 v1 = *(const float2*)&sx[(fr + 8) * 72 + 16 * kt + fc];
            const float2 v2 = *(const float2*)&sx[fr * 72 + 16 * kt + fc + 8];
            const float2 v3 = *(const float2*)&sx[(fr + 8) * 72 + 16 * kt + fc + 8];
            u32 h0 = pkbf(v0.y, v0.x), h1 = pkbf(v1.y, v1.x);
            u32 h2 = pkbf(v2.y, v2.x), h3 = pkbf(v3.y, v3.x);
            xh[kt][0] = h0; xh[kt][1] = h1; xh[kt][2] = h2; xh[kt][3] = h3;
            xl[kt][0] = pkbf(v0.y - bfhi(h0), v0.x - bflo(h0));
            xl[kt][1] = pkbf(v1.y - bfhi(h1), v1.x - bflo(h1));
            xl[kt][2] = pkbf(v2.y - bfhi(h2), v2.x - bflo(h2));
            xl[kt][3] = pkbf(v3.y - bfhi(h3), v3.x - bflo(h3));
        }

        // ---- FFN: 16 hidden k-chunks; split accumulator chains ----
        float4 yacc[8];
        #pragma unroll
        for (int nt = 0; nt < 8; nt++)
            yacc[nt] = make_float4(b2v[nt].x, b2v[nt].y, b2v[nt].x, b2v[nt].y);

        #pragma unroll 1
        for (int hcb = 0; hcb < 16; hcb++) {
            // C: 6 independent accumulator chains (A=xh*Whi+b, B=xh*Wlo, Lz=xl*Whi)
            const float2 b10 = *(const float2*)&sm[OFF_B1 + 16 * hcb + fc];
            const float2 b11 = *(const float2*)&sm[OFF_B1 + 16 * hcb + fc + 8];
            float4 cA0 = make_float4(b10.x, b10.y, b10.x, b10.y);
            float4 cA1 = make_float4(b11.x, b11.y, b11.x, b11.y);
            float4 cB0 = make_float4(0.f, 0.f, 0.f, 0.f);
            float4 cB1 = make_float4(0.f, 0.f, 0.f, 0.f);
            float4 cL0 = make_float4(0.f, 0.f, 0.f, 0.f);
            float4 cL1 = make_float4(0.f, 0.f, 0.f, 0.f);
            #pragma unroll
            for (int kt = 0; kt < 4; kt++) {
                const uint4 w0 = w1f[(kt * 32 + 2 * hcb) * 32 + L];
                const uint4 w1v = w1f[(kt * 32 + 2 * hcb + 1) * 32 + L];
                mma16816(cA0, xh[kt], w0.x, w0.y);
                mma16816(cA1, xh[kt], w1v.x, w1v.y);
                mma16816(cB0, xh[kt], w0.z, w0.w);
                mma16816(cB1, xh[kt], w1v.z, w1v.w);
                mma16816(cL0, xl[kt], w0.x, w0.y);
                mma16816(cL1, xl[kt], w1v.x, w1v.y);
            }
            const float h0 = fmaxf(cA0.x + cB0.x + cL0.x, 0.f), h1 = fmaxf(cA0.y + cB0.y + cL0.y, 0.f);
            const float h2 = fmaxf(cA0.z + cB0.z + cL0.z, 0.f), h3 = fmaxf(cA0.w + cB0.w + cL0.w, 0.f);
            const float h4 = fmaxf(cA1.x + cB1.x + cL1.x, 0.f), h5 = fmaxf(cA1.y + cB1.y + cL1.y, 0.f);
            const float h6 = fmaxf(cA1.z + cB1.z + cL1.z, 0.f), h7 = fmaxf(cA1.w + cB1.w + cL1.w, 0.f);
            u32 hhv[4], hlv[4];
            hhv[0] = pkbf(h1, h0); hhv[1] = pkbf(h3, h2);
            hhv[2] = pkbf(h5, h4); hhv[3] = pkbf(h7, h6);
            hlv[0] = pkbf(h1 - bfhi(hhv[0]), h0 - bflo(hhv[0]));
            hlv[1] = pkbf(h3 - bfhi(hhv[1]), h2 - bflo(hhv[1]));
            hlv[2] = pkbf(h5 - bfhi(hhv[2]), h4 - bflo(hhv[2]));
            hlv[3] = pkbf(h7 - bfhi(hhv[3]), h6 - bflo(hhv[3]));

            // D: term-major — preload 8 W2 fragments, 3 passes over 8 accumulators
            uint4 w2r[8];
            #pragma unroll
            for (int nt = 0; nt < 8; nt++) w2r[nt] = w2f[(hcb * 8 + nt) * 32 + L];
            #pragma unroll
            for (int nt = 0; nt < 8; nt++) mma16816(yacc[nt], hhv, w2r[nt].x, w2r[nt].y);
            #pragma unroll
            for (int nt = 0; nt < 8; nt++) mma16816(yacc[nt], hhv, w2r[nt].z, w2r[nt].w);
            #pragma unroll
            for (int nt = 0; nt < 8; nt++) mma16816(yacc[nt], hlv, w2r[nt].x, w2r[nt].y);
        }

        // ---- LN2 on Y-fragment layout (rows fr, fr+8; 16 ch/row/thread) ----
        {
            float s0 = 0.f, s1 = 0.f;
            #pragma unroll
            for (int nt = 0; nt < 8; nt++) {
                const float2 xa = *(const float2*)&sx[fr * 72 + 8 * nt + fc];
                const float2 xb = *(const float2*)&sx[(fr + 8) * 72 + 8 * nt + fc];
                yacc[nt].x += xa.x; yacc[nt].y += xa.y;
                yacc[nt].z += xb.x; yacc[nt].w += xb.y;
                s0 += yacc[nt].x + yacc[nt].y;
                s1 += yacc[nt].z + yacc[nt].w;
            }
            s0 += __shfl_xor_sync(FULLMASK, s0, 1); s0 += __shfl_xor_sync(FULLMASK, s0, 2);
            s1 += __shfl_xor_sync(FULLMASK, s1, 1); s1 += __shfl_xor_sync(FULLMASK, s1, 2);
            const float mu0 = s0 * (1.0f / 64.0f), mu1 = s1 * (1.0f / 64.0f);
            float q0 = 0.f, q1 = 0.f;
            #pragma unroll
            for (int nt = 0; nt < 8; nt++) {
                float d0 = yacc[nt].x - mu0, d1 = yacc[nt].y - mu0;
                float d2 = yacc[nt].z - mu1, d3 = yacc[nt].w - mu1;
                q0 += d0 * d0 + d1 * d1;
                q1 += d2 * d2 + d3 * d3;
            }
            q0 += __shfl_xor_sync(FULLMASK, q0, 1); q0 += __shfl_xor_sync(FULLMASK, q0, 2);
            q1 += __shfl_xor_sync(FULLMASK, q1, 1); q1 += __shfl_xor_sync(FULLMASK, q1, 2);
            const float rs0 = rsqrtf(fmaf(q0, 1.0f / 64.0f, 1e-5f));
            const float rs1 = rsqrtf(fmaf(q1, 1.0f / 64.0f, 1e-5f));
            #pragma unroll
            for (int nt = 0; nt < 8; nt++) {
                const int ch = 8 * nt + fc;
                const float2 gg = *(const float2*)&sm[OFF_G2 + ch];
                const float2 bb2 = *(const float2*)&sm[OFF_LB2 + ch];
                float2 o0, o1v;
                o0.x = fmaf((yacc[nt].x - mu0) * rs0, gg.x, bb2.x);
                o0.y = fmaf((yacc[nt].y - mu0) * rs0, gg.y, bb2.y);
                o1v.x = fmaf((yacc[nt].z - mu1) * rs1, gg.x, bb2.x);
                o1v.y = fmaf((yacc[nt].w - mu1) * rs1, gg.y, bb2.y);
                *(float2*)&out[(m0 + fr) * 64 + ch]     = o0;
                *(float2*)&out[(m0 + fr + 8) * 64 + ch] = o1v;
            }
        }
        __syncwarp();   // sx reads done before next group's pkb stores
    }
}

extern "C" void kernel_launch(void* const* d_in, const int* in_sizes, int n_in,
                              void* d_out, int out_size) {
    const float* prec = (const float*)d_in[0];
    const int*   msk  = (const int*)d_in[1];
    const float* We   = (const float*)d_in[2];
    const float* be   = (const float*)d_in[3];
    const float* Wq   = (const float*)d_in[4];
    const float* Wk   = (const float*)d_in[5];
    const float* Wv   = (const float*)d_in[6];
    const float* Wo   = (const float*)d_in[7];
    const float* bo   = (const float*)d_in[8];
    const float* g1   = (const float*)d_in[9];
    const float* lb1  = (const float*)d_in[10];
    const float* W1   = (const float*)d_in[11];
    const float* b1   = (const float*)d_in[12];
    const float* W2   = (const float*)d_in[13];
    const float* b2   = (const float*)d_in[14];
    const float* g2   = (const float*)d_in[15];
    const float* lb2  = (const float*)d_in[16];
    float* out = (float*)d_out;

    const int smem_bytes = SMEM_FLOATS * (int)sizeof(float);
    cudaFuncSetAttribute(main_kernel, cudaFuncAttributeMaxDynamicSharedMemorySize, smem_bytes);

    int nsm = 148;
    cudaDeviceGetAttribute(&nsm, cudaDevAttrMultiProcessorCount, 0);

    main_kernel<<<nsm, NTHREADS, smem_bytes>>>(prec, msk, We, be, Wq, Wk, Wv, Wo, bo,
                                               g1, lb1, W1, b1, W2, b2, g2, lb2, out);
}